// round 4
// baseline (speedup 1.0000x reference)
#include <cuda_runtime.h>
#include <cuda_bf16.h>
#include <math.h>
#include <stdint.h>

#define D     64
#define TM    64        // x rows per CTA
#define KP    128       // prototypes (all in every CTA)
#define NTH   256
#define KCAT  192       // 3 concatenated K-chunks of 64: A=[hi,lo,hi], B=[hi,hi,lo]
#define ROWB  384       // bytes per smem row (192 bf16)

// smem byte offsets
#define SM_A   0                         // 64  x 384B = 24576
#define SM_B   24576                     // 128 x 384B = 49152
#define SM_X2  (24576 + 49152)           // 64 floats
#define SM_P2  (SM_X2 + 256)             // 128 floats
#define SM_PS  (SM_P2 + 512)             // 128 floats
#define SM_DYN (SM_PS + 512)             // 75008 B

static __device__ __forceinline__ uint32_t sw(uint32_t off) {
    return off ^ ((off >> 3) & 0x70);
}

static __device__ __forceinline__ uint32_t smem_u32(const void* p) {
    uint32_t a;
    asm("{ .reg .u64 t; cvta.to.shared.u64 t, %1; cvt.u32.u64 %0, t; }" : "=r"(a) : "l"(p));
    return a;
}

static __device__ __forceinline__ void ldsm_x4(uint32_t* r, uint32_t addr) {
    asm volatile("ldmatrix.sync.aligned.m8n8.x4.shared.b16 {%0,%1,%2,%3}, [%4];"
                 : "=r"(r[0]), "=r"(r[1]), "=r"(r[2]), "=r"(r[3]) : "r"(addr));
}

static __device__ __forceinline__ void mma_bf16(float* c, const uint32_t* a,
                                                uint32_t b0, uint32_t b1) {
    asm volatile(
        "mma.sync.aligned.m16n8k16.row.col.f32.bf16.bf16.f32 "
        "{%0,%1,%2,%3}, {%4,%5,%6,%7}, {%8,%9}, {%0,%1,%2,%3};"
        : "+f"(c[0]), "+f"(c[1]), "+f"(c[2]), "+f"(c[3])
        : "r"(a[0]), "r"(a[1]), "r"(a[2]), "r"(a[3]), "r"(b0), "r"(b1));
}

static __device__ __forceinline__ void split2(float v0, float v1,
                                              uint32_t& hi, uint32_t& lo) {
    __nv_bfloat162 h = __floats2bfloat162_rn(v0, v1);
    float r0 = v0 - __bfloat162float(__low2bfloat16(h));
    float r1 = v1 - __bfloat162float(__high2bfloat16(h));
    __nv_bfloat162 l = __floats2bfloat162_rn(r0, r1);
    hi = *reinterpret_cast<uint32_t*>(&h);
    lo = *reinterpret_cast<uint32_t*>(&l);
}

static __device__ __forceinline__ float epi(float xy, float x2, float Bv, float p2) {
    const float A   = 1.0f + p2 - 2.0f * xy;
    float num2 = A * A * x2 - 2.0f * A * Bv * xy + Bv * Bv * p2;
    num2 = fmaxf(num2, 1e-30f);
    const float den = fmaxf(1.0f - 2.0f * xy + x2 * p2, 1e-15f);
    float s = num2 * rsqrtf(num2);          // sqrt(num2): 1 MUFU + 1 mul
    s = fminf(s, 0.99999f * den);           // clamp z <= 1 - 1e-5
    // dist = ln((den+s)/(den-s)) = 2*atanh(z)
    const float dist = (__log2f(den + s) - __log2f(den - s)) * 0.6931471805599453f;
    return -dist * dist;
}

__global__ void __launch_bounds__(NTH)
geo_kernel(const float* __restrict__ x, const float* __restrict__ proto,
           float* __restrict__ out) {
    extern __shared__ char sm[];
    const uint32_t smb = smem_u32(sm);

    const int tid  = threadIdx.x;
    const int wid  = tid >> 5;
    const int lane = tid & 31;
    const int n0   = blockIdx.x * TM;

    float* x2_s = (float*)(sm + SM_X2);
    float* p2_s = (float*)(sm + SM_P2);
    float* ps_s = (float*)(sm + SM_PS);

    // ---- phase 0: exact fp32 norms ----
    if (tid < KP) {
        const float4* p4 = (const float4*)(proto) + (size_t)tid * (D / 4);
        float s = 0.f;
        #pragma unroll
        for (int i = 0; i < D / 4; ++i) {
            float4 v = p4[i];
            s += v.x * v.x + v.y * v.y + v.z * v.z + v.w * v.w;
        }
        float n  = fmaxf(sqrtf(s), 1e-15f);
        float sc = fminf(1.0f, 0.999f / n);   // (1-BALL_EPS)/sqrt(c)
        ps_s[tid] = sc;
        p2_s[tid] = s * sc * sc;
    } else if (tid < KP + TM) {
        int r = tid - KP;
        const float4* x4 = (const float4*)(x + (size_t)(n0 + r) * D);
        float s = 0.f;
        #pragma unroll
        for (int i = 0; i < D / 4; ++i) {
            float4 v = x4[i];
            s += v.x * v.x + v.y * v.y + v.z * v.z + v.w * v.w;
        }
        x2_s[r] = s;
    }
    __syncthreads();

    // ---- phase 1: split-bf16 conversion into swizzled smem ----
    {
        const float2* xs = (const float2*)(x + (size_t)n0 * D);
        #pragma unroll
        for (int it = 0; it < (TM * D / 2) / NTH; ++it) {   // 8 iters
            int idx = it * NTH + tid;
            int row = idx >> 5;        // 32 float2 per row
            int kp  = idx & 31;
            float2 v = xs[row * 32 + kp];
            uint32_t hi, lo;
            split2(v.x, v.y, hi, lo);
            uint32_t base = (uint32_t)row * ROWB + (uint32_t)kp * 4;
            *(uint32_t*)(sm + SM_A + sw(base))       = hi;  // kc0: hi
            *(uint32_t*)(sm + SM_A + sw(base + 128)) = lo;  // kc1: lo
            *(uint32_t*)(sm + SM_A + sw(base + 256)) = hi;  // kc2: hi
        }
        const float2* ps = (const float2*)(proto);
        #pragma unroll
        for (int it = 0; it < (KP * D / 2) / NTH; ++it) {   // 16 iters
            int idx = it * NTH + tid;
            int row = idx >> 5;
            int kp  = idx & 31;
            float sc = ps_s[row];
            float2 v = ps[row * 32 + kp];
            uint32_t hi, lo;
            split2(v.x * sc, v.y * sc, hi, lo);
            uint32_t base = (uint32_t)row * ROWB + (uint32_t)kp * 4;
            *(uint32_t*)(sm + SM_B + sw(base))       = hi;  // kc0: hi
            *(uint32_t*)(sm + SM_B + sw(base + 128)) = hi;  // kc1: hi
            *(uint32_t*)(sm + SM_B + sw(base + 256)) = lo;  // kc2: lo
        }
    }
    __syncthreads();

    // ---- phase 2: warp-tile MMA. warp (wm, wn): rows 16*wm.., cols 64*wn.. ----
    const int wm = wid & 3;
    const int wn = wid >> 2;

    // A ldmatrix lane address: row = wm*16 + (lane&15), k += 8*(lane>>4)
    const int rowA = wm * 16 + (lane & 15);
    const int kA   = (lane >> 4) * 8;
    // B ldmatrix lane address groups of 8 lanes -> (n offset, k offset)
    const int g     = lane >> 3;
    const int nOffB = ((g & 2) ? 8 : 0) + (lane & 7);
    const int kB    = (g & 1) * 8;

    float acc[8][4];
    #pragma unroll
    for (int j = 0; j < 8; ++j)
        #pragma unroll
        for (int u = 0; u < 4; ++u) acc[j][u] = 0.f;

    #pragma unroll
    for (int ks = 0; ks < KCAT / 16; ++ks) {   // 12 k-steps
        const int kg = ks * 16;
        uint32_t a[4];
        ldsm_x4(a, smb + SM_A + sw((uint32_t)rowA * ROWB + (uint32_t)(kg + kA) * 2));
        #pragma unroll
        for (int nb = 0; nb < 4; ++nb) {
            const int nrow = wn * 64 + nb * 16 + nOffB;
            uint32_t b[4];
            ldsm_x4(b, smb + SM_B + sw((uint32_t)nrow * ROWB + (uint32_t)(kg + kB) * 2));
            mma_bf16(acc[2 * nb],     a, b[0], b[1]);
            mma_bf16(acc[2 * nb + 1], a, b[2], b[3]);
        }
    }

    // ---- phase 3: epilogue straight from accumulator regs ----
    {
        const int   ra   = wm * 16 + (lane >> 2);
        const int   rb   = ra + 8;
        const float x2a  = x2_s[ra];
        const float x2b  = x2_s[rb];
        const float Ba   = 1.0f - x2a;
        const float Bb   = 1.0f - x2b;
        float* orowa = out + (size_t)(n0 + ra) * KP;
        float* orowb = out + (size_t)(n0 + rb) * KP;

        #pragma unroll
        for (int j = 0; j < 8; ++j) {
            const int c = wn * 64 + j * 8 + 2 * (lane & 3);
            const float2 p2 = *(const float2*)&p2_s[c];
            float2 oa, ob;
            oa.x = epi(acc[j][0], x2a, Ba, p2.x);
            oa.y = epi(acc[j][1], x2a, Ba, p2.y);
            ob.x = epi(acc[j][2], x2b, Bb, p2.x);
            ob.y = epi(acc[j][3], x2b, Bb, p2.y);
            *(float2*)(orowa + c) = oa;
            *(float2*)(orowb + c) = ob;
        }
    }
}

// ---------------------------------------------------------------------------
extern "C" void kernel_launch(void* const* d_in, const int* in_sizes, int n_in,
                              void* d_out, int out_size) {
    const float* x;
    const float* proto;
    int xs;
    if (in_sizes[0] == KP * D) {
        proto = (const float*)d_in[0];
        x     = (const float*)d_in[1];
        xs    = in_sizes[1];
    } else {
        x     = (const float*)d_in[0];
        proto = (const float*)d_in[1];
        xs    = in_sizes[0];
    }
    const int N = xs / D;  // 16384
    float* out = (float*)d_out;

    cudaFuncSetAttribute(geo_kernel, cudaFuncAttributeMaxDynamicSharedMemorySize, SM_DYN);
    geo_kernel<<<N / TM, NTH, SM_DYN>>>(x, proto, out);
}